// round 4
// baseline (speedup 1.0000x reference)
#include <cuda_runtime.h>

#define DT 0.1f
#define EPSF 1e-6f

// Agents per block == threads per block. R (=131072) must be divisible by TPB.
#define TPB 128
#define JC 64
#define MC 32
#define RSTRIDE 129   // padded smem stride (gcd(129,32)=1 -> conflict-free)

__device__ __forceinline__ float clamp01(float x) {
    return fminf(fmaxf(x, 0.0f), 1.0f);
}

__global__ void __launch_bounds__(TPB, 4) econ_step_kernel(
    const float* __restrict__ need_prev,
    const float* __restrict__ inventory,   // (R, J)
    const float* __restrict__ endowment,   // (R, J)
    const float* __restrict__ price,       // (J, R)
    const float* __restrict__ pool_atp,
    const float* __restrict__ pool_adp,
    const float* __restrict__ pool_amp,
    const float* __restrict__ greed,
    const float* __restrict__ innovation,  // (R, J)
    const float* __restrict__ extraction,  // (R, M)
    const float* __restrict__ deposits,    // (R, M)
    const float* __restrict__ exergy_price,
    const float* __restrict__ bases,       // (3,)
    const float* __restrict__ scales,      // (3,)
    float* __restrict__ out,               // [0,R): gdp, [R,2R): aec
    int R)
{
    __shared__ float s_c[TPB];               // 0.1*DT*aec per agent
    __shared__ float s_ib[TPB];              // innov_budget per agent
    __shared__ float s_q[TPB];               // raw extraction dot per agent
    __shared__ float s_r[JC * RSTRIDE];      // r tile, [col][agent] padded

    const int tid  = threadIdx.x;
    const int lane = tid & 31;
    const int w    = tid >> 5;               // warp id (0..3)
    const int A    = blockIdx.x * TPB;       // first agent of this block
    const int i    = A + tid;                // this thread's agent

    // ---------------- prologue: per-agent scalars (all coalesced) ----------
    const float adp0     = pool_adp[i];
    const float recharge = fminf(adp0, need_prev[i] * DT);
    const float atp      = pool_atp[i] + recharge;
    const float adp      = adp0 - recharge;
    const float amp      = pool_amp[i];
    const float aec      = (atp + 0.5f * adp) / (atp + adp + amp + EPSF);

    const float g       = greed[i];
    const float innov_f = fminf(fmaxf(bases[1] + scales[1] * g, 0.0f), 0.9f);
    const float stor_f  = fminf(fmaxf(bases[2] + scales[2] * g, 0.0f), 0.9f);

    const float wealth  = atp;
    float atp_book      = wealth - wealth * (innov_f + stor_f);

    s_c[tid]  = 0.1f * DT * aec;
    s_ib[tid] = wealth * innov_f * (1.0f / 64.0f);
    __syncthreads();

    // ---------------- extraction: warp-row loads (4 agents / LDG.128) ------
    {
        const float4* ex4 = reinterpret_cast<const float4*>(extraction) + (size_t)A * (MC / 4);
        const float4* dp4 = reinterpret_cast<const float4*>(deposits)   + (size_t)A * (MC / 4);
        // 32 agent-quads per block, 8 iterations per warp
        for (int it = w; it < TPB / 4; it += 4) {
            const size_t idx = (size_t)32 * it + lane;   // 512B contiguous per warp
            const float4 e = ex4[idx];
            const float4 d = dp4[idx];
            float s = e.x * d.x + e.y * d.y + e.z * d.z + e.w * d.w;
            s += __shfl_xor_sync(0xFFFFFFFFu, s, 1);
            s += __shfl_xor_sync(0xFFFFFFFFu, s, 2);
            s += __shfl_xor_sync(0xFFFFFFFFu, s, 4);
            if ((lane & 7) == 0)
                s_q[4 * it + (lane >> 3)] = s;
        }
    }

    // ---------------- production: warp-row loads (2 agents / LDG.128) ------
    {
        const float4* inv4 = reinterpret_cast<const float4*>(inventory)  + (size_t)A * (JC / 4);
        const float4* en4  = reinterpret_cast<const float4*>(endowment)  + (size_t)A * (JC / 4);
        const float4* in4  = reinterpret_cast<const float4*>(innovation) + (size_t)A * (JC / 4);
        // 64 agent-pairs per block, 16 iterations per warp
        for (int it = w; it < TPB / 2; it += 4) {
            const size_t idx = (size_t)32 * it + lane;   // 512B contiguous per warp
            const float4 inv = inv4[idx];
            const float4 en  = en4[idx];
            const float4 nn  = in4[idx];

            const int a_loc = 2 * it + (lane >> 4);      // agent index in block
            const float c   = s_c[a_loc];
            const float ibg = s_ib[a_loc];
            const int  col0 = 4 * (lane & 15);

            const float r0 = c * (nn.x + 0.005f * __fdividef(ibg, 1.0f + nn.x)) * fmaxf(inv.x + DT * en.x, 0.0f);
            const float r1 = c * (nn.y + 0.005f * __fdividef(ibg, 1.0f + nn.y)) * fmaxf(inv.y + DT * en.y, 0.0f);
            const float r2 = c * (nn.z + 0.005f * __fdividef(ibg, 1.0f + nn.z)) * fmaxf(inv.z + DT * en.z, 0.0f);
            const float r3 = c * (nn.w + 0.005f * __fdividef(ibg, 1.0f + nn.w)) * fmaxf(inv.w + DT * en.w, 0.0f);

            float* dst = s_r + a_loc;
            dst[(col0 + 0) * RSTRIDE] = r0;
            dst[(col0 + 1) * RSTRIDE] = r1;
            dst[(col0 + 2) * RSTRIDE] = r2;
            dst[(col0 + 3) * RSTRIDE] = r3;
        }
    }
    __syncthreads();

    // ---------------- finale: per-agent combine (price coalesced) ----------
    float qsum = s_q[tid] * DT;
    const float cost  = qsum * 0.5f;
    const float scale = clamp01(atp_book / (cost + EPSF));
    const float q_scaled_sum = qsum * scale;
    atp_book -= scale * cost;

    float rate_sum = 0.0f;
    float rp_sum   = 0.0f;
    const float* pcol = price + (size_t)A + tid;
    const float* rrow = s_r + tid;
#pragma unroll 8
    for (int k = 0; k < JC; ++k) {
        const float r = rrow[(size_t)k * RSTRIDE];
        const float p = pcol[(size_t)k * R];
        rate_sum += r;
        rp_sum   += r * p;
    }

    const float pcost  = rate_sum * 0.3f;
    const float pscale = clamp01(atp_book / (pcost + EPSF));

    float ep = exergy_price[i] * (1.0f + 0.02f * (0.5f - aec));
    ep = fminf(fmaxf(ep, 1e-4f), 1e4f);

    out[i]     = pscale * rp_sum + q_scaled_sum * ep;
    out[R + i] = aec;
}

extern "C" void kernel_launch(void* const* d_in, const int* in_sizes, int n_in,
                              void* d_out, int out_size) {
    const float* need_prev    = (const float*)d_in[0];
    const float* inventory    = (const float*)d_in[1];
    const float* endowment    = (const float*)d_in[2];
    const float* price        = (const float*)d_in[3];
    const float* pool_atp     = (const float*)d_in[4];
    const float* pool_adp     = (const float*)d_in[5];
    const float* pool_amp     = (const float*)d_in[6];
    const float* greed        = (const float*)d_in[8];
    const float* innovation   = (const float*)d_in[9];
    const float* extraction   = (const float*)d_in[10];
    const float* deposits     = (const float*)d_in[11];
    const float* exergy_price = (const float*)d_in[15];
    const float* bases        = (const float*)d_in[17];
    const float* scales       = (const float*)d_in[18];
    float* out = (float*)d_out;

    const int R = in_sizes[0];           // 131072, divisible by TPB
    const int blocks = R / TPB;
    econ_step_kernel<<<blocks, TPB>>>(
        need_prev, inventory, endowment, price,
        pool_atp, pool_adp, pool_amp, greed,
        innovation, extraction, deposits, exergy_price,
        bases, scales, out, R);
}

// round 7
// speedup vs baseline: 1.2597x; 1.2597x over previous
#include <cuda_runtime.h>

#define DT 0.1f
#define EPSF 1e-6f
#define TPB 128   // 4 warps; warp w owns agents [A+32w, A+32w+32)

__device__ __forceinline__ float clamp01(float x) {
    return fminf(fmaxf(x, 0.0f), 1.0f);
}

__global__ void __launch_bounds__(TPB, 6) econ_step_kernel(
    const float* __restrict__ need_prev,
    const float* __restrict__ inventory,   // (R, 64)
    const float* __restrict__ endowment,   // (R, 64)
    const float* __restrict__ price,       // (64, R)
    const float* __restrict__ pool_atp,
    const float* __restrict__ pool_adp,
    const float* __restrict__ pool_amp,
    const float* __restrict__ greed,
    const float* __restrict__ innovation,  // (R, 64)
    const float* __restrict__ extraction,  // (R, 32)
    const float* __restrict__ deposits,    // (R, 32)
    const float* __restrict__ exergy_price,
    const float* __restrict__ bases,       // (3,)
    const float* __restrict__ scales,      // (3,)
    float* __restrict__ out,               // [0,R): gdp, [R,2R): aec
    int R)
{
    // Per-warp r-tile: 64 cols x 32 agents, XOR-swizzled (no padding needed).
    __shared__ float s_tile[4 * 64 * 32];   // 32 KB
    __shared__ float s_q[TPB];              // extraction dot per agent

    const int tid  = threadIdx.x;
    const int lane = tid & 31;
    const int w    = tid >> 5;
    const int A    = blockIdx.x * TPB;
    const int i    = A + tid;               // this thread's agent
    const int aw   = A + 32 * w;            // warp's first agent

    const float4* inv4 = reinterpret_cast<const float4*>(inventory)  + (size_t)aw * 16;
    const float4* en4  = reinterpret_cast<const float4*>(endowment)  + (size_t)aw * 16;
    const float4* in4  = reinterpret_cast<const float4*>(innovation) + (size_t)aw * 16;

    // Prefetch first production group early (raises MLP during extraction).
    const float4 pf_inv = inv4[lane];
    const float4 pf_en  = en4[lane];
    const float4 pf_nn  = in4[lane];

    // ---------------- prologue: per-agent scalars (warp-local) -------------
    const float adp0     = pool_adp[i];
    const float recharge = fminf(adp0, need_prev[i] * DT);
    const float atp      = pool_atp[i] + recharge;
    const float adp      = adp0 - recharge;
    const float amp      = pool_amp[i];
    const float aec      = (atp + 0.5f * adp) / (atp + adp + amp + EPSF);

    const float g       = greed[i];
    const float innov_f = fminf(fmaxf(bases[1] + scales[1] * g, 0.0f), 0.9f);
    const float stor_f  = fminf(fmaxf(bases[2] + scales[2] * g, 0.0f), 0.9f);

    const float wealth  = atp;
    float atp_book      = wealth - wealth * (innov_f + stor_f);

    const float my_c  = 0.01f * aec;                       // 0.1*DT*aec
    const float my_ib = wealth * innov_f * (1.0f / 64.0f); // innov_budget

    // ---------------- extraction: warp-row loads, warp-local ---------------
    {
        const float4* ex4 = reinterpret_cast<const float4*>(extraction) + (size_t)aw * 8;
        const float4* dp4 = reinterpret_cast<const float4*>(deposits)   + (size_t)aw * 8;
#pragma unroll
        for (int t = 0; t < 8; ++t) {          // agents 4t..4t+3 (local)
            const int idx = t * 32 + lane;     // 512B contiguous per warp
            const float4 e = ex4[idx];
            const float4 d = dp4[idx];
            float s = e.x * d.x + e.y * d.y + e.z * d.z + e.w * d.w;
            s += __shfl_xor_sync(0xFFFFFFFFu, s, 1);
            s += __shfl_xor_sync(0xFFFFFFFFu, s, 2);
            s += __shfl_xor_sync(0xFFFFFFFFu, s, 4);
            if ((lane & 7) == 0)
                s_q[32 * w + 4 * t + (lane >> 3)] = s;
        }
    }

    // ---------------- production: warp-row loads -> swizzled tile ----------
    {
        float* tile = s_tile + w * 2048;

        const int h  = lane >> 4;              // which agent of the pair
        const int q0 = 4 * (lane & 15);        // first col this lane handles

        // Peeled t = 0 using the prefetched registers.
        {
            const int la  = h;
            const float c  = __shfl_sync(0xFFFFFFFFu, my_c,  la);
            const float ib = __shfl_sync(0xFFFFFFFFu, my_ib, la);

            const float r0 = c * (pf_nn.x + 0.005f * __fdividef(ib, 1.0f + pf_nn.x)) * fmaxf(pf_inv.x + DT * pf_en.x, 0.0f);
            const float r1 = c * (pf_nn.y + 0.005f * __fdividef(ib, 1.0f + pf_nn.y)) * fmaxf(pf_inv.y + DT * pf_en.y, 0.0f);
            const float r2 = c * (pf_nn.z + 0.005f * __fdividef(ib, 1.0f + pf_nn.z)) * fmaxf(pf_inv.z + DT * pf_en.z, 0.0f);
            const float r3 = c * (pf_nn.w + 0.005f * __fdividef(ib, 1.0f + pf_nn.w)) * fmaxf(pf_inv.w + DT * pf_en.w, 0.0f);

            tile[(q0 + 0) * 32 + ((la + q0 + 0) & 31)] = r0;
            tile[(q0 + 1) * 32 + ((la + q0 + 1) & 31)] = r1;
            tile[(q0 + 2) * 32 + ((la + q0 + 2) & 31)] = r2;
            tile[(q0 + 3) * 32 + ((la + q0 + 3) & 31)] = r3;
        }

#pragma unroll 5
        for (int t = 1; t < 16; ++t) {         // agent pair (2t, 2t+1) local
            const int idx = t * 32 + lane;     // 512B contiguous per warp
            const float4 inv = inv4[idx];
            const float4 en  = en4[idx];
            const float4 nn  = in4[idx];

            const int la  = 2 * t + h;         // local agent index (0..31)
            const float c  = __shfl_sync(0xFFFFFFFFu, my_c,  la);
            const float ib = __shfl_sync(0xFFFFFFFFu, my_ib, la);

            const float r0 = c * (nn.x + 0.005f * __fdividef(ib, 1.0f + nn.x)) * fmaxf(inv.x + DT * en.x, 0.0f);
            const float r1 = c * (nn.y + 0.005f * __fdividef(ib, 1.0f + nn.y)) * fmaxf(inv.y + DT * en.y, 0.0f);
            const float r2 = c * (nn.z + 0.005f * __fdividef(ib, 1.0f + nn.z)) * fmaxf(inv.z + DT * en.z, 0.0f);
            const float r3 = c * (nn.w + 0.005f * __fdividef(ib, 1.0f + nn.w)) * fmaxf(inv.w + DT * en.w, 0.0f);

            // tile[col][agent], swizzled: addr = col*32 + ((agent + col) & 31)
            tile[(q0 + 0) * 32 + ((la + q0 + 0) & 31)] = r0;
            tile[(q0 + 1) * 32 + ((la + q0 + 1) & 31)] = r1;
            tile[(q0 + 2) * 32 + ((la + q0 + 2) & 31)] = r2;
            tile[(q0 + 3) * 32 + ((la + q0 + 3) & 31)] = r3;
        }
    }
    __syncwarp();   // all tile/s_q producers are in this warp

    // ---------------- finale: per-agent combine (price coalesced) ----------
    float qsum = s_q[tid] * DT;
    const float cost  = qsum * 0.5f;
    const float scale = clamp01(atp_book / (cost + EPSF));
    const float q_scaled_sum = qsum * scale;
    atp_book -= scale * cost;

    const float* tile = s_tile + w * 2048;
    const float* pcol = price + (size_t)i;

    float rate_sum = 0.0f;
    float rp_sum   = 0.0f;
#pragma unroll 8
    for (int k = 0; k < 64; ++k) {
        const float r = tile[k * 32 + ((lane + k) & 31)];
        const float p = pcol[(size_t)k * R];
        rate_sum += r;
        rp_sum   += r * p;
    }

    const float pcost  = rate_sum * 0.3f;
    const float pscale = clamp01(atp_book / (pcost + EPSF));

    float ep = exergy_price[i] * (1.0f + 0.02f * (0.5f - aec));
    ep = fminf(fmaxf(ep, 1e-4f), 1e4f);

    out[i]     = pscale * rp_sum + q_scaled_sum * ep;
    out[R + i] = aec;
}

extern "C" void kernel_launch(void* const* d_in, const int* in_sizes, int n_in,
                              void* d_out, int out_size) {
    const float* need_prev    = (const float*)d_in[0];
    const float* inventory    = (const float*)d_in[1];
    const float* endowment    = (const float*)d_in[2];
    const float* price        = (const float*)d_in[3];
    const float* pool_atp     = (const float*)d_in[4];
    const float* pool_adp     = (const float*)d_in[5];
    const float* pool_amp     = (const float*)d_in[6];
    const float* greed        = (const float*)d_in[8];
    const float* innovation   = (const float*)d_in[9];
    const float* extraction   = (const float*)d_in[10];
    const float* deposits     = (const float*)d_in[11];
    const float* exergy_price = (const float*)d_in[15];
    const float* bases        = (const float*)d_in[17];
    const float* scales       = (const float*)d_in[18];
    float* out = (float*)d_out;

    const int R = in_sizes[0];   // 131072, divisible by TPB
    const int blocks = R / TPB;
    econ_step_kernel<<<blocks, TPB>>>(
        need_prev, inventory, endowment, price,
        pool_atp, pool_adp, pool_amp, greed,
        innovation, extraction, deposits, exergy_price,
        bases, scales, out, R);
}

// round 8
// speedup vs baseline: 1.4991x; 1.1901x over previous
#include <cuda_runtime.h>

#define DT 0.1f
#define EPSF 1e-6f
#define TPB 256   // 8 warps = 4 warp-pairs; pair p owns agents [A+32p, A+32p+32)

__device__ __forceinline__ float clamp01(float x) {
    return fminf(fmaxf(x, 0.0f), 1.0f);
}

__global__ void __launch_bounds__(TPB, 5) econ_step_kernel(
    const float* __restrict__ need_prev,
    const float* __restrict__ inventory,   // (R, 64)
    const float* __restrict__ endowment,   // (R, 64)
    const float* __restrict__ price,       // (64, R)
    const float* __restrict__ pool_atp,
    const float* __restrict__ pool_adp,
    const float* __restrict__ pool_amp,
    const float* __restrict__ greed,
    const float* __restrict__ innovation,  // (R, 64)
    const float* __restrict__ extraction,  // (R, 32)
    const float* __restrict__ deposits,    // (R, 32)
    const float* __restrict__ exergy_price,
    const float* __restrict__ bases,       // (3,)
    const float* __restrict__ scales,      // (3,)
    float* __restrict__ out,               // [0,R): gdp, [R,2R): aec
    int R)
{
    // Per-pair r-tile: 64 cols x 32 agents, XOR-swizzled.
    __shared__ float s_tile[4 * 64 * 32];   // 32 KB
    __shared__ float s_q[128];              // extraction dot per agent (block has 128 agents)
    __shared__ float s_rate[4 * 32];        // warp-odd partial rate_sum
    __shared__ float s_rp[4 * 32];          // warp-odd partial rp_sum

    const int tid  = threadIdx.x;
    const int lane = tid & 31;
    const int w    = tid >> 5;
    const int p    = w >> 1;                // warp pair (0..3)
    const int h    = w & 1;                 // column half
    const int A    = blockIdx.x * 128;      // 128 agents per block
    const int aw   = A + 32 * p;            // pair's first agent
    const int i    = aw + lane;             // this lane's agent (redundant per pair)

    // ---------------- prologue: per-agent scalars (redundant in pair) ------
    const float adp0     = pool_adp[i];
    const float recharge = fminf(adp0, need_prev[i] * DT);
    const float atp      = pool_atp[i] + recharge;
    const float adp      = adp0 - recharge;
    const float amp      = pool_amp[i];
    const float aec      = (atp + 0.5f * adp) / (atp + adp + amp + EPSF);

    const float g       = greed[i];
    const float innov_f = fminf(fmaxf(bases[1] + scales[1] * g, 0.0f), 0.9f);
    const float stor_f  = fminf(fmaxf(bases[2] + scales[2] * g, 0.0f), 0.9f);

    const float wealth  = atp;
    float atp_book      = wealth - wealth * (innov_f + stor_f);

    const float my_c  = 0.01f * aec;                       // 0.1*DT*aec
    const float my_ib = wealth * innov_f * (1.0f / 64.0f); // innov_budget

    // ---------------- extraction: warp handles agents [16h, 16h+16) --------
    {
        const float4* ex4 = reinterpret_cast<const float4*>(extraction) + (size_t)aw * 8;
        const float4* dp4 = reinterpret_cast<const float4*>(deposits)   + (size_t)aw * 8;
#pragma unroll
        for (int t = 0; t < 4; ++t) {
            const int la  = 16 * h + 4 * t + (lane >> 3);  // local agent
            const int idx = la * 8 + (lane & 7);
            const float4 e = ex4[idx];
            const float4 d = dp4[idx];
            float s = e.x * d.x + e.y * d.y + e.z * d.z + e.w * d.w;
            s += __shfl_xor_sync(0xFFFFFFFFu, s, 1);
            s += __shfl_xor_sync(0xFFFFFFFFu, s, 2);
            s += __shfl_xor_sync(0xFFFFFFFFu, s, 4);
            if ((lane & 7) == 0)
                s_q[32 * p + la] = s;
        }
    }

    // ---------------- production: warp handles cols [32h, 32h+32) ----------
    float* tile = s_tile + p * 2048;
    {
        const float4* inv4 = reinterpret_cast<const float4*>(inventory)  + (size_t)aw * 16 + h * 8;
        const float4* en4  = reinterpret_cast<const float4*>(endowment)  + (size_t)aw * 16 + h * 8;
        const float4* in4  = reinterpret_cast<const float4*>(innovation) + (size_t)aw * 16 + h * 8;

        const int la_of = lane >> 3;            // which of 4 agents this lane
        const int f     = lane & 7;             // float4 index in half-row
        const int col0  = 32 * h + 4 * f;       // first col this lane handles

#pragma unroll 4
        for (int t = 0; t < 8; ++t) {           // 4 agents per iteration
            const int la  = 4 * t + la_of;      // local agent (0..31)
            const int idx = la * 16 + f;
            const float4 inv = inv4[idx];
            const float4 en  = en4[idx];
            const float4 nn  = in4[idx];

            const float c  = __shfl_sync(0xFFFFFFFFu, my_c,  la);
            const float ib = __shfl_sync(0xFFFFFFFFu, my_ib, la);

            const float r0 = c * (nn.x + 0.005f * __fdividef(ib, 1.0f + nn.x)) * fmaxf(inv.x + DT * en.x, 0.0f);
            const float r1 = c * (nn.y + 0.005f * __fdividef(ib, 1.0f + nn.y)) * fmaxf(inv.y + DT * en.y, 0.0f);
            const float r2 = c * (nn.z + 0.005f * __fdividef(ib, 1.0f + nn.z)) * fmaxf(inv.z + DT * en.z, 0.0f);
            const float r3 = c * (nn.w + 0.005f * __fdividef(ib, 1.0f + nn.w)) * fmaxf(inv.w + DT * en.w, 0.0f);

            // tile[col][agent], swizzled: addr = col*32 + ((agent + col) & 31)
            tile[(col0 + 0) * 32 + ((la + col0 + 0) & 31)] = r0;
            tile[(col0 + 1) * 32 + ((la + col0 + 1) & 31)] = r1;
            tile[(col0 + 2) * 32 + ((la + col0 + 2) & 31)] = r2;
            tile[(col0 + 3) * 32 + ((la + col0 + 3) & 31)] = r3;
        }
    }
    __syncwarp();   // tile cols [32h,32h+32) written entirely by this warp

    // ---------------- per-warp partial sums over own 32 cols ---------------
    // lane = agent; cols [32h, 32h+32); price loads coalesced across lanes.
    float rate_p = 0.0f;
    float rp_p   = 0.0f;
    {
        const float* pcol = price + (size_t)(32 * h) * R + i;
#pragma unroll 8
        for (int k = 0; k < 32; ++k) {
            const int col = 32 * h + k;
            const float r  = tile[col * 32 + ((lane + col) & 31)];
            const float pr = pcol[(size_t)k * R];
            rate_p += r;
            rp_p   += r * pr;
        }
    }

    if (h == 1) {
        s_rate[32 * p + lane] = rate_p;
        s_rp[32 * p + lane]   = rp_p;
    }
    __syncthreads();   // the only block-wide barrier

    // ---------------- finale: warp-even combines + epilogue ----------------
    if (h == 0) {
        const float rate_sum = rate_p + s_rate[32 * p + lane];
        const float rp_sum   = rp_p   + s_rp[32 * p + lane];

        float qsum = s_q[32 * p + lane] * DT;
        const float cost  = qsum * 0.5f;
        const float scale = clamp01(atp_book / (cost + EPSF));
        const float q_scaled_sum = qsum * scale;
        atp_book -= scale * cost;

        const float pcost  = rate_sum * 0.3f;
        const float pscale = clamp01(atp_book / (pcost + EPSF));

        float ep = exergy_price[i] * (1.0f + 0.02f * (0.5f - aec));
        ep = fminf(fmaxf(ep, 1e-4f), 1e4f);

        out[i]     = pscale * rp_sum + q_scaled_sum * ep;
        out[R + i] = aec;
    }
}

extern "C" void kernel_launch(void* const* d_in, const int* in_sizes, int n_in,
                              void* d_out, int out_size) {
    const float* need_prev    = (const float*)d_in[0];
    const float* inventory    = (const float*)d_in[1];
    const float* endowment    = (const float*)d_in[2];
    const float* price        = (const float*)d_in[3];
    const float* pool_atp     = (const float*)d_in[4];
    const float* pool_adp     = (const float*)d_in[5];
    const float* pool_amp     = (const float*)d_in[6];
    const float* greed        = (const float*)d_in[8];
    const float* innovation   = (const float*)d_in[9];
    const float* extraction   = (const float*)d_in[10];
    const float* deposits     = (const float*)d_in[11];
    const float* exergy_price = (const float*)d_in[15];
    const float* bases        = (const float*)d_in[17];
    const float* scales       = (const float*)d_in[18];
    float* out = (float*)d_out;

    const int R = in_sizes[0];       // 131072; 128 agents per block
    const int blocks = R / 128;
    econ_step_kernel<<<blocks, TPB>>>(
        need_prev, inventory, endowment, price,
        pool_atp, pool_adp, pool_amp, greed,
        innovation, extraction, deposits, exergy_price,
        bases, scales, out, R);
}